// round 2
// baseline (speedup 1.0000x reference)
#include <cuda_runtime.h>
#include <math.h>

// ---------------- problem constants ----------------
#define BQ     2
#define LQ     2048
#define DMODEL 2048
#define NH     16
#define DH     128          // head dim (key)
#define HV     256          // head dim (value)
#define NPROJ  12320        // total projection cols
#define MROWS  (BQ*LQ)      // 4096 token rows
// proj column layout: q[0,2048) k[2048,4096) v[4096,8192) gate[8192,12288) b[12288,12304) A[12304,12320)

// ---------------- scratch (static device allocations) ----------------
__device__ float g_proj[(size_t)MROWS * NPROJ];   // ~202 MB
__device__ float g_q  [(size_t)MROWS * 2048];
__device__ float g_k  [(size_t)MROWS * 2048];
__device__ float g_v  [(size_t)MROWS * 4096];
__device__ float g_g  [MROWS * NH];
__device__ float g_b  [MROWS * NH];

// ============================================================
// Kernel 1: fp32 GEMM  C[M,N] = A[M,K] @ B[K,N]
// 128x128 tile, BK=8, 256 threads, 8x8 microtile,
// double-buffered shared tiles (prefetch k+1 while computing k)
// ============================================================
__global__ __launch_bounds__(256) void gemm128(const float* __restrict__ A,
                                               const float* __restrict__ B)
{
    const int Kq = DMODEL, Nq = NPROJ;
    __shared__ float As[2][8][128];
    __shared__ float Bs[2][8][128];

    int tid  = threadIdx.x;
    int row0 = blockIdx.y * 128;
    int col0 = blockIdx.x * 128;

    int a_row = tid >> 1;            // 128 rows, 2 thr/row
    int a_k   = (tid & 1) * 4;       // float4 within BK=8
    int b_k   = tid >> 5;            // 8 k rows
    int b_n   = (tid & 31) * 4;      // float4 across 128 cols

    int tr = (tid >> 4) * 8;         // microtile row
    int tc = (tid & 15) * 8;         // microtile col

    float acc[8][8];
#pragma unroll
    for (int i = 0; i < 8; i++)
#pragma unroll
        for (int j = 0; j < 8; j++) acc[i][j] = 0.f;

    const float* Aptr = A + (size_t)(row0 + a_row) * Kq + a_k;
    bool bok = (col0 + b_n) < Nq;
    const float* Bptr = B + (size_t)b_k * Nq + col0 + b_n;

    // preload k0 = 0 into buffer 0
    {
        float4 av = *(const float4*)(Aptr);
        float4 bv = make_float4(0.f, 0.f, 0.f, 0.f);
        if (bok) bv = *(const float4*)(Bptr);
        As[0][a_k + 0][a_row] = av.x;
        As[0][a_k + 1][a_row] = av.y;
        As[0][a_k + 2][a_row] = av.z;
        As[0][a_k + 3][a_row] = av.w;
        *(float4*)&Bs[0][b_k][b_n] = bv;
    }
    __syncthreads();

    int buf = 0;
    for (int k0 = 8; k0 <= Kq; k0 += 8) {
        float4 av, bv;
        bool more = (k0 < Kq);
        if (more) {
            av = *(const float4*)(Aptr + k0);
            bv = make_float4(0.f, 0.f, 0.f, 0.f);
            if (bok) bv = *(const float4*)(Bptr + (size_t)k0 * Nq);
        }

#pragma unroll
        for (int kk = 0; kk < 8; kk++) {
            float ar[8], br[8];
            *(float4*)(ar)     = *(const float4*)&As[buf][kk][tr];
            *(float4*)(ar + 4) = *(const float4*)&As[buf][kk][tr + 4];
            *(float4*)(br)     = *(const float4*)&Bs[buf][kk][tc];
            *(float4*)(br + 4) = *(const float4*)&Bs[buf][kk][tc + 4];
#pragma unroll
            for (int i = 0; i < 8; i++)
#pragma unroll
                for (int j = 0; j < 8; j++)
                    acc[i][j] = fmaf(ar[i], br[j], acc[i][j]);
        }

        if (more) {
            int nb = buf ^ 1;
            As[nb][a_k + 0][a_row] = av.x;
            As[nb][a_k + 1][a_row] = av.y;
            As[nb][a_k + 2][a_row] = av.z;
            As[nb][a_k + 3][a_row] = av.w;
            *(float4*)&Bs[nb][b_k][b_n] = bv;
            __syncthreads();
            buf = nb;
        }
    }

#pragma unroll
    for (int i = 0; i < 8; i++) {
        size_t r = (size_t)(row0 + tr + i);
#pragma unroll
        for (int j4 = 0; j4 < 8; j4 += 4) {
            int c = col0 + tc + j4;
            if (c < Nq)
                *(float4*)&g_proj[r * Nq + c] =
                    make_float4(acc[i][j4], acc[i][j4 + 1], acc[i][j4 + 2], acc[i][j4 + 3]);
        }
    }
}

// ============================================================
// Kernel 2: causal depthwise conv4 + SiLU + per-head l2norm (q,k)
//           + beta/g scalar math
// one block per token row m, 512 threads
// ============================================================
__device__ __forceinline__ float conv_silu(const float* __restrict__ Wc, int m, int t, int c)
{
    float acc = 0.f;
#pragma unroll
    for (int j = 0; j < 4; j++) {
        int tt = t - 3 + j;
        if (tt >= 0)
            acc = fmaf(g_proj[(size_t)(m - 3 + j) * NPROJ + c], Wc[c * 4 + j], acc);
    }
    return acc / (1.f + __expf(-acc));  // silu
}

__global__ __launch_bounds__(512) void conv_kernel(const float* __restrict__ Wc,
                                                   const float* __restrict__ A_log,
                                                   const float* __restrict__ dt_bias)
{
    int m   = blockIdx.x;
    int t   = m & (LQ - 1);
    int tid = threadIdx.x;

    __shared__ float ssum[32];   // [0,16): q head sumsq, [16,32): k head sumsq
    if (tid < 32) ssum[tid] = 0.f;
    __syncthreads();

    float yq[4], yk[4];
#pragma unroll
    for (int r = 0; r < 4; r++) {          // q channels
        int c = tid + r * 512;             // 0..2047
        float y = conv_silu(Wc, m, t, c);
        yq[r] = y;
        atomicAdd(&ssum[c >> 7], y * y);
    }
#pragma unroll
    for (int r = 0; r < 4; r++) {          // k channels
        int cl = tid + r * 512;            // local 0..2047
        float y = conv_silu(Wc, m, t, 2048 + cl);
        yk[r] = y;
        atomicAdd(&ssum[16 + (cl >> 7)], y * y);
    }
#pragma unroll
    for (int r = 0; r < 8; r++) {          // v channels
        int cl = tid + r * 512;            // local 0..4095
        g_v[(size_t)m * 4096 + cl] = conv_silu(Wc, m, t, 4096 + cl);
    }
    if (tid < NH) {
        float bv = g_proj[(size_t)m * NPROJ + 12288 + tid];
        float av = g_proj[(size_t)m * NPROJ + 12304 + tid] + dt_bias[tid];
        float sp = (av > 20.f) ? av : log1pf(expf(av));
        g_b[m * NH + tid] = 1.f / (1.f + expf(-bv));
        g_g[m * NH + tid] = -expf(A_log[tid]) * sp;
    }
    __syncthreads();

#pragma unroll
    for (int r = 0; r < 4; r++) {
        int c = tid + r * 512;
        g_q[(size_t)m * 2048 + c] = yq[r] * rsqrtf(ssum[c >> 7] + 1e-6f);
    }
#pragma unroll
    for (int r = 0; r < 4; r++) {
        int c = tid + r * 512;
        g_k[(size_t)m * 2048 + c] = yk[r] * rsqrtf(ssum[16 + (c >> 7)] + 1e-6f);
    }
}

// ============================================================
// Kernel 3: sequential delta-rule scan + output gating
// one warp per (b, h, v-group of 8); lane owns 4 k-rows -> S[4][8] in regs
// 1024 warps total; no block syncs, pure warp shuffles
// ============================================================
__global__ __launch_bounds__(128) void scan_kernel(float* __restrict__ out)
{
    int gw   = (blockIdx.x * blockDim.x + threadIdx.x) >> 5;
    int lane = threadIdx.x & 31;
    int bh = gw >> 5;            // 0..31
    int vg = gw & 31;            // 0..31  (8 v-cols each)
    int b = bh >> 4;
    int h = bh & 15;
    const float scale = 0.08838834764831845f;  // 1/sqrt(128)

    float S[4][8];
#pragma unroll
    for (int i = 0; i < 4; i++)
#pragma unroll
        for (int j = 0; j < 8; j++) S[i][j] = 0.f;

    size_t row = (size_t)b * LQ;
    const float* kp  = g_k + row * 2048 + h * 128 + lane * 4;
    const float* qp  = g_q + row * 2048 + h * 128 + lane * 4;
    const float* vp  = g_v + row * 4096 + h * 256 + vg * 8;
    const float* gp  = g_g + row * NH + h;
    const float* bp  = g_b + row * NH + h;
    const float* gatep = g_proj + row * NPROJ + 8192 + h * 256 + vg * 8;
    float* op = out + row * 4096 + h * 256 + vg * 8;

    for (int t = 0; t < LQ; t++) {
        float4 k4 = *(const float4*)kp;  kp += 2048;
        float4 q4 = *(const float4*)qp;  qp += 2048;
        float4 va = *(const float4*)vp;
        float4 vb = *(const float4*)(vp + 4);  vp += 4096;
        float gt = *gp;  gp += NH;
        float bt = *bp;  bp += NH;

        float dec = __expf(gt);
        float kr[4] = {k4.x, k4.y, k4.z, k4.w};

        float kv[8];
#pragma unroll
        for (int j = 0; j < 8; j++) kv[j] = 0.f;
#pragma unroll
        for (int i = 0; i < 4; i++)
#pragma unroll
            for (int j = 0; j < 8; j++) {
                S[i][j] *= dec;
                kv[j] = fmaf(kr[i], S[i][j], kv[j]);
            }
#pragma unroll
        for (int off = 16; off > 0; off >>= 1)
#pragma unroll
            for (int j = 0; j < 8; j++)
                kv[j] += __shfl_xor_sync(0xFFFFFFFFu, kv[j], off);

        float vt[8] = {va.x, va.y, va.z, va.w, vb.x, vb.y, vb.z, vb.w};
        float qr[4] = {q4.x * scale, q4.y * scale, q4.z * scale, q4.w * scale};

        float o8[8];
#pragma unroll
        for (int j = 0; j < 8; j++) {
            float d = (vt[j] - kv[j]) * bt;
            o8[j] = 0.f;
#pragma unroll
            for (int i = 0; i < 4; i++) {
                S[i][j] = fmaf(kr[i], d, S[i][j]);
                o8[j] = fmaf(qr[i], S[i][j], o8[j]);
            }
        }
#pragma unroll
        for (int off = 16; off > 0; off >>= 1)
#pragma unroll
            for (int j = 0; j < 8; j++)
                o8[j] += __shfl_xor_sync(0xFFFFFFFFu, o8[j], off);

        if (lane == 0) {
            float4 ga = *(const float4*)gatep;
            float4 gbv = *(const float4*)(gatep + 4);
            float gv[8] = {ga.x, ga.y, ga.z, ga.w, gbv.x, gbv.y, gbv.z, gbv.w};
            float r[8];
#pragma unroll
            for (int j = 0; j < 8; j++)
                r[j] = o8[j] * (gv[j] / (1.f + __expf(-gv[j])));
            *(float4*)op       = make_float4(r[0], r[1], r[2], r[3]);
            *(float4*)(op + 4) = make_float4(r[4], r[5], r[6], r[7]);
        }
        gatep += NPROJ;
        op += 4096;
    }
}

// ============================================================
extern "C" void kernel_launch(void* const* d_in, const int* in_sizes, int n_in,
                              void* d_out, int out_size)
{
    const float* hidden  = (const float*)d_in[0];
    const float* W       = (const float*)d_in[1];
    const float* Wconv   = (const float*)d_in[2];
    const float* A_log   = (const float*)d_in[3];
    const float* dt_bias = (const float*)d_in[4];
    float* out = (float*)d_out;

    dim3 ggrid((NPROJ + 127) / 128, MROWS / 128);   // 97 x 32
    gemm128<<<ggrid, 256>>>(hidden, W);

    conv_kernel<<<MROWS, 512>>>(Wconv, A_log, dt_bias);

    scan_kernel<<<256, 128>>>(out);
}

// round 3
// speedup vs baseline: 1.0050x; 1.0050x over previous
#include <cuda_runtime.h>
#include <math.h>

// ---------------- problem constants ----------------
#define BQ     2
#define LQ     2048
#define DMODEL 2048
#define NH     16
#define DH     128          // head dim (key)
#define HV     256          // head dim (value)
#define NPROJ  12320        // total projection cols
#define MROWS  (BQ*LQ)      // 4096 token rows
// proj column layout: q[0,2048) k[2048,4096) v[4096,8192) gate[8192,12288) b[12288,12304) A[12304,12320)

// ---------------- scratch (static device allocations) ----------------
__device__ float g_proj[(size_t)MROWS * NPROJ];   // ~202 MB
__device__ float g_q  [(size_t)MROWS * 2048];
__device__ float g_k  [(size_t)MROWS * 2048];
__device__ float g_v  [(size_t)MROWS * 4096];
__device__ float g_g  [MROWS * NH];
__device__ float g_b  [MROWS * NH];

// ============================================================
// Kernel 1: fp32 GEMM  C[M,N] = A[M,K] @ B[K,N]
// 128x128 tile, BK=8, 256 threads, 8x8 microtile,
// double-buffered shared tiles (prefetch k+1 while computing k)
// ============================================================
__global__ __launch_bounds__(256) void gemm128(const float* __restrict__ A,
                                               const float* __restrict__ B)
{
    const int Kq = DMODEL, Nq = NPROJ;
    __shared__ float As[2][8][128];
    __shared__ float Bs[2][8][128];

    int tid  = threadIdx.x;
    int row0 = blockIdx.y * 128;
    int col0 = blockIdx.x * 128;

    int a_row = tid >> 1;            // 128 rows, 2 thr/row
    int a_k   = (tid & 1) * 4;       // float4 within BK=8
    int b_k   = tid >> 5;            // 8 k rows
    int b_n   = (tid & 31) * 4;      // float4 across 128 cols

    int tr = (tid >> 4) * 8;         // microtile row
    int tc = (tid & 15) * 8;         // microtile col

    float acc[8][8];
#pragma unroll
    for (int i = 0; i < 8; i++)
#pragma unroll
        for (int j = 0; j < 8; j++) acc[i][j] = 0.f;

    const float* Aptr = A + (size_t)(row0 + a_row) * Kq + a_k;
    bool bok = (col0 + b_n) < Nq;
    const float* Bptr = B + (size_t)b_k * Nq + col0 + b_n;

    // preload k0 = 0 into buffer 0
    {
        float4 av = *(const float4*)(Aptr);
        float4 bv = make_float4(0.f, 0.f, 0.f, 0.f);
        if (bok) bv = *(const float4*)(Bptr);
        As[0][a_k + 0][a_row] = av.x;
        As[0][a_k + 1][a_row] = av.y;
        As[0][a_k + 2][a_row] = av.z;
        As[0][a_k + 3][a_row] = av.w;
        *(float4*)&Bs[0][b_k][b_n] = bv;
    }
    __syncthreads();

    int buf = 0;
    for (int k0 = 8; k0 <= Kq; k0 += 8) {
        float4 av, bv;
        bool more = (k0 < Kq);
        if (more) {
            av = *(const float4*)(Aptr + k0);
            bv = make_float4(0.f, 0.f, 0.f, 0.f);
            if (bok) bv = *(const float4*)(Bptr + (size_t)k0 * Nq);
        }

#pragma unroll
        for (int kk = 0; kk < 8; kk++) {
            float ar[8], br[8];
            *(float4*)(ar)     = *(const float4*)&As[buf][kk][tr];
            *(float4*)(ar + 4) = *(const float4*)&As[buf][kk][tr + 4];
            *(float4*)(br)     = *(const float4*)&Bs[buf][kk][tc];
            *(float4*)(br + 4) = *(const float4*)&Bs[buf][kk][tc + 4];
#pragma unroll
            for (int i = 0; i < 8; i++)
#pragma unroll
                for (int j = 0; j < 8; j++)
                    acc[i][j] = fmaf(ar[i], br[j], acc[i][j]);
        }

        if (more) {
            int nb = buf ^ 1;
            As[nb][a_k + 0][a_row] = av.x;
            As[nb][a_k + 1][a_row] = av.y;
            As[nb][a_k + 2][a_row] = av.z;
            As[nb][a_k + 3][a_row] = av.w;
            *(float4*)&Bs[nb][b_k][b_n] = bv;
            __syncthreads();
            buf = nb;
        }
    }

#pragma unroll
    for (int i = 0; i < 8; i++) {
        size_t r = (size_t)(row0 + tr + i);
#pragma unroll
        for (int j4 = 0; j4 < 8; j4 += 4) {
            int c = col0 + tc + j4;
            if (c < Nq)
                *(float4*)&g_proj[r * Nq + c] =
                    make_float4(acc[i][j4], acc[i][j4 + 1], acc[i][j4 + 2], acc[i][j4 + 3]);
        }
    }
}

// ============================================================
// Kernel 2: causal depthwise conv4 + SiLU + per-head l2norm (q,k)
//           + beta/g scalar math
// one block per token row m, 512 threads
// ============================================================
__device__ __forceinline__ float conv_silu(const float* __restrict__ Wc, int m, int t, int c)
{
    float acc = 0.f;
#pragma unroll
    for (int j = 0; j < 4; j++) {
        int tt = t - 3 + j;
        if (tt >= 0)
            acc = fmaf(g_proj[(size_t)(m - 3 + j) * NPROJ + c], Wc[c * 4 + j], acc);
    }
    return acc / (1.f + __expf(-acc));  // silu
}

__global__ __launch_bounds__(512) void conv_kernel(const float* __restrict__ Wc,
                                                   const float* __restrict__ A_log,
                                                   const float* __restrict__ dt_bias)
{
    int m   = blockIdx.x;
    int t   = m & (LQ - 1);
    int tid = threadIdx.x;

    __shared__ float ssum[32];   // [0,16): q head sumsq, [16,32): k head sumsq
    if (tid < 32) ssum[tid] = 0.f;
    __syncthreads();

    float yq[4], yk[4];
#pragma unroll
    for (int r = 0; r < 4; r++) {          // q channels
        int c = tid + r * 512;             // 0..2047
        float y = conv_silu(Wc, m, t, c);
        yq[r] = y;
        atomicAdd(&ssum[c >> 7], y * y);
    }
#pragma unroll
    for (int r = 0; r < 4; r++) {          // k channels
        int cl = tid + r * 512;            // local 0..2047
        float y = conv_silu(Wc, m, t, 2048 + cl);
        yk[r] = y;
        atomicAdd(&ssum[16 + (cl >> 7)], y * y);
    }
#pragma unroll
    for (int r = 0; r < 8; r++) {          // v channels
        int cl = tid + r * 512;            // local 0..4095
        g_v[(size_t)m * 4096 + cl] = conv_silu(Wc, m, t, 4096 + cl);
    }
    if (tid < NH) {
        float bv = g_proj[(size_t)m * NPROJ + 12288 + tid];
        float av = g_proj[(size_t)m * NPROJ + 12304 + tid] + dt_bias[tid];
        float sp = (av > 20.f) ? av : log1pf(expf(av));
        g_b[m * NH + tid] = 1.f / (1.f + expf(-bv));
        g_g[m * NH + tid] = -expf(A_log[tid]) * sp;
    }
    __syncthreads();

#pragma unroll
    for (int r = 0; r < 4; r++) {
        int c = tid + r * 512;
        g_q[(size_t)m * 2048 + c] = yq[r] * rsqrtf(ssum[c >> 7] + 1e-6f);
    }
#pragma unroll
    for (int r = 0; r < 4; r++) {
        int c = tid + r * 512;
        g_k[(size_t)m * 2048 + c] = yk[r] * rsqrtf(ssum[16 + (c >> 7)] + 1e-6f);
    }
}

// ============================================================
// Kernel 3: sequential delta-rule scan + output gating
// one warp per (b, h, v-group of 8); lane owns 4 k-rows -> S[4][8] in regs
// 1024 warps total; no block syncs, pure warp shuffles
// ============================================================
__global__ __launch_bounds__(128) void scan_kernel(float* __restrict__ out)
{
    int gw   = (blockIdx.x * blockDim.x + threadIdx.x) >> 5;
    int lane = threadIdx.x & 31;
    int bh = gw >> 5;            // 0..31
    int vg = gw & 31;            // 0..31  (8 v-cols each)
    int b = bh >> 4;
    int h = bh & 15;
    const float scale = 0.08838834764831845f;  // 1/sqrt(128)

    float S[4][8];
#pragma unroll
    for (int i = 0; i < 4; i++)
#pragma unroll
        for (int j = 0; j < 8; j++) S[i][j] = 0.f;

    size_t row = (size_t)b * LQ;
    const float* kp  = g_k + row * 2048 + h * 128 + lane * 4;
    const float* qp  = g_q + row * 2048 + h * 128 + lane * 4;
    const float* vp  = g_v + row * 4096 + h * 256 + vg * 8;
    const float* gp  = g_g + row * NH + h;
    const float* bp  = g_b + row * NH + h;
    const float* gatep = g_proj + row * NPROJ + 8192 + h * 256 + vg * 8;
    float* op = out + row * 4096 + h * 256 + vg * 8;

    for (int t = 0; t < LQ; t++) {
        float4 k4 = *(const float4*)kp;  kp += 2048;
        float4 q4 = *(const float4*)qp;  qp += 2048;
        float4 va = *(const float4*)vp;
        float4 vb = *(const float4*)(vp + 4);  vp += 4096;
        float gt = *gp;  gp += NH;
        float bt = *bp;  bp += NH;

        float dec = __expf(gt);
        float kr[4] = {k4.x, k4.y, k4.z, k4.w};

        float kv[8];
#pragma unroll
        for (int j = 0; j < 8; j++) kv[j] = 0.f;
#pragma unroll
        for (int i = 0; i < 4; i++)
#pragma unroll
            for (int j = 0; j < 8; j++) {
                S[i][j] *= dec;
                kv[j] = fmaf(kr[i], S[i][j], kv[j]);
            }
#pragma unroll
        for (int off = 16; off > 0; off >>= 1)
#pragma unroll
            for (int j = 0; j < 8; j++)
                kv[j] += __shfl_xor_sync(0xFFFFFFFFu, kv[j], off);

        float vt[8] = {va.x, va.y, va.z, va.w, vb.x, vb.y, vb.z, vb.w};
        float qr[4] = {q4.x * scale, q4.y * scale, q4.z * scale, q4.w * scale};

        float o8[8];
#pragma unroll
        for (int j = 0; j < 8; j++) {
            float d = (vt[j] - kv[j]) * bt;
            o8[j] = 0.f;
#pragma unroll
            for (int i = 0; i < 4; i++) {
                S[i][j] = fmaf(kr[i], d, S[i][j]);
                o8[j] = fmaf(qr[i], S[i][j], o8[j]);
            }
        }
#pragma unroll
        for (int off = 16; off > 0; off >>= 1)
#pragma unroll
            for (int j = 0; j < 8; j++)
                o8[j] += __shfl_xor_sync(0xFFFFFFFFu, o8[j], off);

        if (lane == 0) {
            float4 ga = *(const float4*)gatep;
            float4 gbv = *(const float4*)(gatep + 4);
            float gv[8] = {ga.x, ga.y, ga.z, ga.w, gbv.x, gbv.y, gbv.z, gbv.w};
            float r[8];
#pragma unroll
            for (int j = 0; j < 8; j++)
                r[j] = o8[j] * (gv[j] / (1.f + __expf(-gv[j])));
            *(float4*)op       = make_float4(r[0], r[1], r[2], r[3]);
            *(float4*)(op + 4) = make_float4(r[4], r[5], r[6], r[7]);
        }
        gatep += NPROJ;
        op += 4096;
    }
}

// ============================================================
extern "C" void kernel_launch(void* const* d_in, const int* in_sizes, int n_in,
                              void* d_out, int out_size)
{
    const float* hidden  = (const float*)d_in[0];
    const float* W       = (const float*)d_in[1];
    const float* Wconv   = (const float*)d_in[2];
    const float* A_log   = (const float*)d_in[3];
    const float* dt_bias = (const float*)d_in[4];
    float* out = (float*)d_out;

    dim3 ggrid((NPROJ + 127) / 128, MROWS / 128);   // 97 x 32
    gemm128<<<ggrid, 256>>>(hidden, W);

    conv_kernel<<<MROWS, 512>>>(Wconv, A_log, dt_bias);

    scan_kernel<<<256, 128>>>(out);
}

// round 5
// speedup vs baseline: 1.1962x; 1.1902x over previous
#include <cuda_runtime.h>
#include <math.h>
#include <stdint.h>

// ---------------- problem constants ----------------
#define BQ     2
#define LQ     2048
#define DMODEL 2048
#define NH     16
#define DH     128          // head dim (key)
#define HV     256          // head dim (value)
#define NPROJ  12320        // total projection cols
#define MROWS  (BQ*LQ)      // 4096 token rows
// proj column layout: q[0,2048) k[2048,4096) v[4096,8192) gate[8192,12288) b[12288,12304) A[12304,12320)

// ---------------- scratch (static device allocations) ----------------
__device__ float g_proj[(size_t)MROWS * NPROJ];   // ~202 MB
__device__ float g_q  [(size_t)MROWS * 2048];
__device__ float g_k  [(size_t)MROWS * 2048];
__device__ float g_v  [(size_t)MROWS * 4096];
__device__ float g_g  [MROWS * NH];
__device__ float g_b  [MROWS * NH];

// ============================================================
// Kernel 1: tensor-core GEMM  C[M,N] = A[M,K] @ B[K,N]  (3xTF32 split)
// Block tile 128x128, BK=16, 256 threads (8 warps, warp tile 32x64),
// double-buffered shared, mma.sync.m16n8k8.tf32, fp32 accumulate.
// hi = tf32(x), lo = tf32(x - hi); C += Ahi*Bhi + Ahi*Blo + Alo*Bhi
// ============================================================
#define BKS 16
#define SPAD 132   // shared row pitch (floats)

__device__ __forceinline__ uint32_t f2tf32(float x) {
    uint32_t r;
    asm("cvt.rna.tf32.f32 %0, %1;" : "=r"(r) : "f"(x));
    return r;
}

__device__ __forceinline__ void mma_tf32(float c[4],
                                         uint32_t a0, uint32_t a1, uint32_t a2, uint32_t a3,
                                         uint32_t b0, uint32_t b1)
{
    asm volatile(
        "mma.sync.aligned.m16n8k8.row.col.f32.tf32.tf32.f32 "
        "{%0,%1,%2,%3}, {%4,%5,%6,%7}, {%8,%9}, {%0,%1,%2,%3};\n"
        : "+f"(c[0]), "+f"(c[1]), "+f"(c[2]), "+f"(c[3])
        : "r"(a0), "r"(a1), "r"(a2), "r"(a3), "r"(b0), "r"(b1));
}

__global__ __launch_bounds__(256, 1) void gemm_tf32(const float* __restrict__ A,
                                                    const float* __restrict__ B)
{
    const int Kq = DMODEL, Nq = NPROJ;
    __shared__ float As[2][BKS][SPAD];   // [k][m]
    __shared__ float Bs[2][BKS][SPAD];   // [k][n]

    const int tid  = threadIdx.x;
    const int lane = tid & 31;
    const int wid  = tid >> 5;
    const int gid  = lane >> 2;      // 0..7
    const int tig  = lane & 3;       // 0..3

    const int m0 = (wid & 3) * 32;   // warp m origin in tile
    const int n0 = (wid >> 2) * 64;  // warp n origin in tile

    const int row0 = blockIdx.y * 128;
    const int col0 = blockIdx.x * 128;

    // global load indexing
    const int arow1 = tid >> 2;           // 0..63
    const int ak1   = (tid & 3) * 4;      // 0,4,8,12
    const int brow1 = tid >> 5;           // 0..7
    const int bn1   = (tid & 31) * 4;     // 0..124

    const float* Ap = A + (size_t)(row0 + arow1) * Kq + ak1;          // + 64*Kq for 2nd
    const bool bok  = (col0 + bn1) < Nq;
    const float* Bp = B + (size_t)brow1 * Nq + col0 + bn1;            // + 8*Nq for 2nd

    float c[2][8][4];
#pragma unroll
    for (int mt = 0; mt < 2; mt++)
#pragma unroll
        for (int nt = 0; nt < 8; nt++)
#pragma unroll
            for (int e = 0; e < 4; e++) c[mt][nt][e] = 0.f;

    // ---- preload k0=0 into buffer 0 ----
    {
        float4 av0 = *(const float4*)(Ap);
        float4 av1 = *(const float4*)(Ap + (size_t)64 * Kq);
        float4 bv0 = make_float4(0.f,0.f,0.f,0.f), bv1 = bv0;
        if (bok) {
            bv0 = *(const float4*)(Bp);
            bv1 = *(const float4*)(Bp + (size_t)8 * Nq);
        }
        As[0][ak1+0][arow1] = av0.x; As[0][ak1+1][arow1] = av0.y;
        As[0][ak1+2][arow1] = av0.z; As[0][ak1+3][arow1] = av0.w;
        As[0][ak1+0][arow1+64] = av1.x; As[0][ak1+1][arow1+64] = av1.y;
        As[0][ak1+2][arow1+64] = av1.z; As[0][ak1+3][arow1+64] = av1.w;
        *(float4*)&Bs[0][brow1][bn1]   = bv0;
        *(float4*)&Bs[0][brow1+8][bn1] = bv1;
    }
    __syncthreads();

    int buf = 0;
    for (int k0 = BKS; k0 <= Kq; k0 += BKS) {
        float4 av0, av1, bv0, bv1;
        const bool more = (k0 < Kq);
        if (more) {
            av0 = *(const float4*)(Ap + k0);
            av1 = *(const float4*)(Ap + (size_t)64 * Kq + k0);
            bv0 = make_float4(0.f,0.f,0.f,0.f); bv1 = bv0;
            if (bok) {
                bv0 = *(const float4*)(Bp + (size_t)k0 * Nq);
                bv1 = *(const float4*)(Bp + (size_t)(k0 + 8) * Nq);
            }
        }

        // ---- compute on buffer `buf`: two k=8 sub-steps ----
#pragma unroll
        for (int ks = 0; ks < 2; ks++) {
            const int kb = ks * 8;

            // A fragments (hi/lo) for 2 m-tiles
            uint32_t ahi[2][4], alo[2][4];
#pragma unroll
            for (int mt = 0; mt < 2; mt++) {
                const int mbase = m0 + mt * 16 + gid;
#pragma unroll
                for (int e = 0; e < 4; e++) {
                    const int kk = kb + tig + ((e >> 1) ? 4 : 0);
                    const int mm = mbase + ((e & 1) ? 8 : 0);
                    const float x = As[buf][kk][mm];
                    const uint32_t h = f2tf32(x);
                    ahi[mt][e] = h;
                    alo[mt][e] = f2tf32(x - __uint_as_float(h));
                }
            }
            // B fragments (hi/lo) for 8 n-tiles
            uint32_t bhi[8][2], blo[8][2];
#pragma unroll
            for (int nt = 0; nt < 8; nt++) {
                const int nn = n0 + nt * 8 + gid;
#pragma unroll
                for (int e = 0; e < 2; e++) {
                    const int kk = kb + tig + e * 4;
                    const float x = Bs[buf][kk][nn];
                    const uint32_t h = f2tf32(x);
                    bhi[nt][e] = h;
                    blo[nt][e] = f2tf32(x - __uint_as_float(h));
                }
            }
            // 3-term MMAs
#pragma unroll
            for (int mt = 0; mt < 2; mt++)
#pragma unroll
                for (int nt = 0; nt < 8; nt++) {
                    mma_tf32(c[mt][nt], ahi[mt][0], ahi[mt][1], ahi[mt][2], ahi[mt][3],
                             blo[nt][0], blo[nt][1]);
                    mma_tf32(c[mt][nt], alo[mt][0], alo[mt][1], alo[mt][2], alo[mt][3],
                             bhi[nt][0], bhi[nt][1]);
                    mma_tf32(c[mt][nt], ahi[mt][0], ahi[mt][1], ahi[mt][2], ahi[mt][3],
                             bhi[nt][0], bhi[nt][1]);
                }
        }

        if (more) {
            const int nb = buf ^ 1;
            As[nb][ak1+0][arow1] = av0.x; As[nb][ak1+1][arow1] = av0.y;
            As[nb][ak1+2][arow1] = av0.z; As[nb][ak1+3][arow1] = av0.w;
            As[nb][ak1+0][arow1+64] = av1.x; As[nb][ak1+1][arow1+64] = av1.y;
            As[nb][ak1+2][arow1+64] = av1.z; As[nb][ak1+3][arow1+64] = av1.w;
            *(float4*)&Bs[nb][brow1][bn1]   = bv0;
            *(float4*)&Bs[nb][brow1+8][bn1] = bv1;
            __syncthreads();
            buf = nb;
        }
    }

    // ---- epilogue: scattered float2 stores ----
#pragma unroll
    for (int mt = 0; mt < 2; mt++) {
        const int rbase = row0 + m0 + mt * 16 + gid;
#pragma unroll
        for (int nt = 0; nt < 8; nt++) {
            const int cc = col0 + n0 + nt * 8 + 2 * tig;
            if (cc < Nq) {
                *(float2*)&g_proj[(size_t)rbase * Nq + cc] =
                    make_float2(c[mt][nt][0], c[mt][nt][1]);
                *(float2*)&g_proj[(size_t)(rbase + 8) * Nq + cc] =
                    make_float2(c[mt][nt][2], c[mt][nt][3]);
            }
        }
    }
}

// ============================================================
// Kernel 2: causal depthwise conv4 + SiLU + per-head l2norm (q,k)
//           + beta/g scalar math
// one block per token row m, 512 threads
// ============================================================
__device__ __forceinline__ float conv_silu(const float* __restrict__ Wc, int m, int t, int c)
{
    float acc = 0.f;
#pragma unroll
    for (int j = 0; j < 4; j++) {
        int tt = t - 3 + j;
        if (tt >= 0)
            acc = fmaf(g_proj[(size_t)(m - 3 + j) * NPROJ + c], Wc[c * 4 + j], acc);
    }
    return acc / (1.f + __expf(-acc));  // silu
}

__global__ __launch_bounds__(512) void conv_kernel(const float* __restrict__ Wc,
                                                   const float* __restrict__ A_log,
                                                   const float* __restrict__ dt_bias)
{
    int m   = blockIdx.x;
    int t   = m & (LQ - 1);
    int tid = threadIdx.x;

    __shared__ float ssum[32];   // [0,16): q head sumsq, [16,32): k head sumsq
    if (tid < 32) ssum[tid] = 0.f;
    __syncthreads();

    float yq[4], yk[4];
#pragma unroll
    for (int r = 0; r < 4; r++) {          // q channels
        int c = tid + r * 512;             // 0..2047
        float y = conv_silu(Wc, m, t, c);
        yq[r] = y;
        atomicAdd(&ssum[c >> 7], y * y);
    }
#pragma unroll
    for (int r = 0; r < 4; r++) {          // k channels
        int cl = tid + r * 512;            // local 0..2047
        float y = conv_silu(Wc, m, t, 2048 + cl);
        yk[r] = y;
        atomicAdd(&ssum[16 + (cl >> 7)], y * y);
    }
#pragma unroll
    for (int r = 0; r < 8; r++) {          // v channels
        int cl = tid + r * 512;            // local 0..4095
        g_v[(size_t)m * 4096 + cl] = conv_silu(Wc, m, t, 4096 + cl);
    }
    if (tid < NH) {
        float bv = g_proj[(size_t)m * NPROJ + 12288 + tid];
        float av = g_proj[(size_t)m * NPROJ + 12304 + tid] + dt_bias[tid];
        float sp = (av > 20.f) ? av : log1pf(expf(av));
        g_b[m * NH + tid] = 1.f / (1.f + expf(-bv));
        g_g[m * NH + tid] = -expf(A_log[tid]) * sp;
    }
    __syncthreads();

#pragma unroll
    for (int r = 0; r < 4; r++) {
        int c = tid + r * 512;
        g_q[(size_t)m * 2048 + c] = yq[r] * rsqrtf(ssum[c >> 7] + 1e-6f);
    }
#pragma unroll
    for (int r = 0; r < 4; r++) {
        int c = tid + r * 512;
        g_k[(size_t)m * 2048 + c] = yk[r] * rsqrtf(ssum[16 + (c >> 7)] + 1e-6f);
    }
}

// ============================================================
// Kernel 3: sequential delta-rule scan + output gating
// one warp per (b, h, v-group of 8); lane owns 4 k-rows -> S[4][8] in regs
// 1024 warps total; no block syncs, pure warp shuffles
// ============================================================
__global__ __launch_bounds__(128) void scan_kernel(float* __restrict__ out)
{
    int gw   = (blockIdx.x * blockDim.x + threadIdx.x) >> 5;
    int lane = threadIdx.x & 31;
    int bh = gw >> 5;            // 0..31
    int vg = gw & 31;            // 0..31  (8 v-cols each)
    int b = bh >> 4;
    int h = bh & 15;
    const float scale = 0.08838834764831845f;  // 1/sqrt(128)

    float S[4][8];
#pragma unroll
    for (int i = 0; i < 4; i++)
#pragma unroll
        for (int j = 0; j < 8; j++) S[i][j] = 0.f;

    size_t row = (size_t)b * LQ;
    const float* kp  = g_k + row * 2048 + h * 128 + lane * 4;
    const float* qp  = g_q + row * 2048 + h * 128 + lane * 4;
    const float* vp  = g_v + row * 4096 + h * 256 + vg * 8;
    const float* gp  = g_g + row * NH + h;
    const float* bp  = g_b + row * NH + h;
    const float* gatep = g_proj + row * NPROJ + 8192 + h * 256 + vg * 8;
    float* op = out + row * 4096 + h * 256 + vg * 8;

    for (int t = 0; t < LQ; t++) {
        float4 k4 = *(const float4*)kp;  kp += 2048;
        float4 q4 = *(const float4*)qp;  qp += 2048;
        float4 va = *(const float4*)vp;
        float4 vb = *(const float4*)(vp + 4);  vp += 4096;
        float gt = *gp;  gp += NH;
        float bt = *bp;  bp += NH;

        float dec = __expf(gt);
        float kr[4] = {k4.x, k4.y, k4.z, k4.w};

        float kv[8];
#pragma unroll
        for (int j = 0; j < 8; j++) kv[j] = 0.f;
#pragma unroll
        for (int i = 0; i < 4; i++)
#pragma unroll
            for (int j = 0; j < 8; j++) {
                S[i][j] *= dec;
                kv[j] = fmaf(kr[i], S[i][j], kv[j]);
            }
#pragma unroll
        for (int off = 16; off > 0; off >>= 1)
#pragma unroll
            for (int j = 0; j < 8; j++)
                kv[j] += __shfl_xor_sync(0xFFFFFFFFu, kv[j], off);

        float vt[8] = {va.x, va.y, va.z, va.w, vb.x, vb.y, vb.z, vb.w};
        float qr[4] = {q4.x * scale, q4.y * scale, q4.z * scale, q4.w * scale};

        float o8[8];
#pragma unroll
        for (int j = 0; j < 8; j++) {
            float d = (vt[j] - kv[j]) * bt;
            o8[j] = 0.f;
#pragma unroll
            for (int i = 0; i < 4; i++) {
                S[i][j] = fmaf(kr[i], d, S[i][j]);
                o8[j] = fmaf(qr[i], S[i][j], o8[j]);
            }
        }
#pragma unroll
        for (int off = 16; off > 0; off >>= 1)
#pragma unroll
            for (int j = 0; j < 8; j++)
                o8[j] += __shfl_xor_sync(0xFFFFFFFFu, o8[j], off);

        if (lane == 0) {
            float4 ga = *(const float4*)gatep;
            float4 gbv = *(const float4*)(gatep + 4);
            float gv[8] = {ga.x, ga.y, ga.z, ga.w, gbv.x, gbv.y, gbv.z, gbv.w};
            float r[8];
#pragma unroll
            for (int j = 0; j < 8; j++)
                r[j] = o8[j] * (gv[j] / (1.f + __expf(-gv[j])));
            *(float4*)op       = make_float4(r[0], r[1], r[2], r[3]);
            *(float4*)(op + 4) = make_float4(r[4], r[5], r[6], r[7]);
        }
        gatep += NPROJ;
        op += 4096;
    }
}

// ============================================================
extern "C" void kernel_launch(void* const* d_in, const int* in_sizes, int n_in,
                              void* d_out, int out_size)
{
    const float* hidden  = (const float*)d_in[0];
    const float* W       = (const float*)d_in[1];
    const float* Wconv   = (const float*)d_in[2];
    const float* A_log   = (const float*)d_in[3];
    const float* dt_bias = (const float*)d_in[4];
    float* out = (float*)d_out;

    dim3 ggrid((NPROJ + 127) / 128, MROWS / 128);   // 97 x 32
    gemm_tf32<<<ggrid, 256>>>(hidden, W);

    conv_kernel<<<MROWS, 512>>>(Wconv, A_log, dt_bias);

    scan_kernel<<<256, 128>>>(out);
}